// round 13
// baseline (speedup 1.0000x reference)
#include <cuda_runtime.h>
#include <cuda_fp16.h>
#include <cstdint>

// out[b,n] = sum_{c,hw} x[b,c,hw] * W_s[n,hw] * W_d[n,c] + W_b[n]
// GEMM D[(b,c),n] = x . Ws^T via fp16 mma.sync m16n8k16 (fp32 accum).
// BOTH operands pre-converted to fp16 (one streaming prep kernel) so all
// fragments come via ldmatrix — no in-loop cvt, minimal crossbar traffic.
// BM=BN=128, 256 thr, 2 CTAs/SM, BK=32, 4 stages. Split-K {800,800,800,736}.
// Fused Wd epilogue via atomics (out pre-set to W_b in prep).

#define M_DIM 8192
#define N_DIM 1024
#define K_DIM 3136
#define BM 128
#define BN 128
#define STAGES 4
#define A_ROW_B 80                     // 32 halfs + 16B pad -> conflict-free ldmatrix
#define B_ROW_B 80
#define A_ST_BYTES (128 * A_ROW_B)     // 10240
#define B_ST_BYTES (128 * B_ROW_B)     // 10240
#define ST_BYTES   (A_ST_BYTES + B_ST_BYTES)   // 20480
#define SMEM_BYTES (STAGES * ST_BYTES)         // 81920 (x2 CTA = 160KB/SM)

__device__ __align__(16) __half g_Ah[(size_t)M_DIM * K_DIM];  // 51.4 MB fp16 x
__device__ __align__(16) __half g_Bh[(size_t)N_DIM * K_DIM];  // 6.4 MB fp16 Ws

__device__ __forceinline__ void cp_async16(void* s, const void* g) {
    uint32_t sa = (uint32_t)__cvta_generic_to_shared(s);
    asm volatile("cp.async.cg.shared.global [%0], [%1], 16;\n" :: "r"(sa), "l"(g));
}
__device__ __forceinline__ uint32_t pack_h2(float lo, float hi) {
    __half2 h = __floats2half2_rn(lo, hi);
    return *reinterpret_cast<uint32_t*>(&h);
}

// -------- prep: x->fp16 (6272 blocks), Ws->fp16 (784), out=W_b (2) --------
__global__ __launch_bounds__(256)
void prep_all(const float* __restrict__ x, const float* __restrict__ Ws,
              const float* __restrict__ Wb, float* __restrict__ out) {
    const int bid = blockIdx.x;
    const int tid = threadIdx.x;
    if (bid < 6272) {                       // x: 6,422,528 float4s
        const size_t base = (size_t)bid * 1024 + tid;
        float4 v[4];
        #pragma unroll
        for (int j = 0; j < 4; j++)
            v[j] = reinterpret_cast<const float4*>(x)[base + j * 256];
        #pragma unroll
        for (int j = 0; j < 4; j++) {
            uint2 o;
            o.x = pack_h2(v[j].x, v[j].y);
            o.y = pack_h2(v[j].z, v[j].w);
            reinterpret_cast<uint2*>(g_Ah)[base + j * 256] = o;
        }
    } else if (bid < 7056) {                // Ws: 802,816 float4s
        const size_t base = (size_t)(bid - 6272) * 1024 + tid;
        float4 v[4];
        #pragma unroll
        for (int j = 0; j < 4; j++)
            v[j] = reinterpret_cast<const float4*>(Ws)[base + j * 256];
        #pragma unroll
        for (int j = 0; j < 4; j++) {
            uint2 o;
            o.x = pack_h2(v[j].x, v[j].y);
            o.y = pack_h2(v[j].z, v[j].w);
            reinterpret_cast<uint2*>(g_Bh)[base + j * 256] = o;
        }
    } else {                                // out init: 8192 float4s
        const int idx = (bid - 7056) * 256 + tid;   // 0..511
        #pragma unroll
        for (int j = 0; j < 16; j++) {
            int oi = idx * 16 + j;
            reinterpret_cast<float4*>(out)[oi] =
                reinterpret_cast<const float4*>(Wb)[oi & 255];
        }
    }
}

// ---------------- fused GEMM ----------------
__global__ __launch_bounds__(256, 2)
void gemm_fused(const float* __restrict__ Wd, float* __restrict__ out) {
    extern __shared__ char smem[];

    const int tid  = threadIdx.x;
    const int warp = tid >> 5;      // 0..7
    const int lane = tid & 31;
    const int wm   = warp & 3;      // 4 warps along M (32 rows)
    const int wn   = warp >> 2;     // 2 warps along N (64 cols)
    const int g    = lane >> 2;
    const int t4   = lane & 3;

    const int gx = blockIdx.x;      // 0..7  N tile
    const int gy = blockIdx.y;      // 0..63 M tile
    const int sp = blockIdx.z;      // 0..3  K split
    const int b  = gy >> 1;
    const int c0 = (gy & 1) * BM;

    const int kst  = sp * 800;
    const int NT32 = (sp == 3) ? 23 : 25;

    // cp.async: A 512 chunks (2/thread), B 512 chunks (2/thread)
    const int row0 = tid >> 2, off0 = (tid & 3);           // chunks tid, tid+256
    const int row1 = (tid + 256) >> 2;
    const __half* apt0 = g_Ah + (size_t)(gy * BM + row0) * K_DIM + kst + off0 * 8;
    const __half* apt1 = g_Ah + (size_t)(gy * BM + row1) * K_DIM + kst + off0 * 8;
    const __half* bpt0 = g_Bh + (size_t)(gx * BN + row0) * K_DIM + kst + off0 * 8;
    const __half* bpt1 = g_Bh + (size_t)(gx * BN + row1) * K_DIM + kst + off0 * 8;

    // ldmatrix lane maps
    const int a_row = (lane & 7) + ((lane >> 3) & 1) * 8;   // 0..15
    const int a_ko  = (lane >> 4) & 1;                      // k-chunk 0/1
    const int b_row = ((lane >> 4) & 1) * 8 + (lane & 7);
    const int b_half = ((lane >> 3) & 1) * 8;

    float acc[2][8][4];
    #pragma unroll
    for (int i = 0; i < 2; i++)
        #pragma unroll
        for (int j = 0; j < 8; j++)
            #pragma unroll
            for (int k = 0; k < 4; k++) acc[i][j][k] = 0.f;

    auto load_stage = [&](int s, int kt) {
        char* st = smem + s * ST_BYTES;
        cp_async16(st + row0 * A_ROW_B + off0 * 16, apt0 + kt * 32);
        cp_async16(st + row1 * A_ROW_B + off0 * 16, apt1 + kt * 32);
        cp_async16(st + A_ST_BYTES + row0 * B_ROW_B + off0 * 16, bpt0 + kt * 32);
        cp_async16(st + A_ST_BYTES + row1 * B_ROW_B + off0 * 16, bpt1 + kt * 32);
    };

    load_stage(0, 0);
    asm volatile("cp.async.commit_group;\n" ::: "memory");
    load_stage(1, 1);
    asm volatile("cp.async.commit_group;\n" ::: "memory");
    load_stage(2, 2);
    asm volatile("cp.async.commit_group;\n" ::: "memory");

    int s_cur = 0, s_load = 3;
    #pragma unroll 1
    for (int kt = 0; kt < NT32; ++kt) {
        asm volatile("cp.async.wait_group 2;\n" ::: "memory");
        __syncthreads();

        if (kt + 3 < NT32) load_stage(s_load, kt + 3);
        asm volatile("cp.async.commit_group;\n" ::: "memory");

        const char* st  = smem + s_cur * ST_BYTES;
        const uint32_t smA = (uint32_t)__cvta_generic_to_shared(st);
        const uint32_t smB = smA + A_ST_BYTES;

        uint32_t af0[2][4], af1[2][4], bf0[8][2], bf1[8][2];

        // ---- h0 B frags ----
        #pragma unroll
        for (int np = 0; np < 4; np++) {
            uint32_t addr = smB + ((wn * 64 + np * 16 + b_row) * B_ROW_B) + (b_half * 2);
            asm volatile(
                "ldmatrix.sync.aligned.m8n8.x4.shared.b16 {%0,%1,%2,%3}, [%4];\n"
                : "=r"(bf0[2 * np][0]), "=r"(bf0[2 * np][1]),
                  "=r"(bf0[2 * np + 1][0]), "=r"(bf0[2 * np + 1][1])
                : "r"(addr));
        }
        // ---- h0 A frags ----
        #pragma unroll
        for (int mi = 0; mi < 2; mi++) {
            uint32_t addr = smA + ((wm * 32 + mi * 16 + a_row) * A_ROW_B) + (a_ko * 16);
            asm volatile(
                "ldmatrix.sync.aligned.m8n8.x4.shared.b16 {%0,%1,%2,%3}, [%4];\n"
                : "=r"(af0[mi][0]), "=r"(af0[mi][1]), "=r"(af0[mi][2]), "=r"(af0[mi][3])
                : "r"(addr));
        }
        // ---- h1 B frags (prefetch before h0 MMAs) ----
        #pragma unroll
        for (int np = 0; np < 4; np++) {
            uint32_t addr = smB + ((wn * 64 + np * 16 + b_row) * B_ROW_B) + ((16 + b_half) * 2);
            asm volatile(
                "ldmatrix.sync.aligned.m8n8.x4.shared.b16 {%0,%1,%2,%3}, [%4];\n"
                : "=r"(bf1[2 * np][0]), "=r"(bf1[2 * np][1]),
                  "=r"(bf1[2 * np + 1][0]), "=r"(bf1[2 * np + 1][1])
                : "r"(addr));
        }
        // ---- h0 MMAs ----
        #pragma unroll
        for (int mi = 0; mi < 2; mi++)
            #pragma unroll
            for (int ni = 0; ni < 8; ni++) {
                asm volatile(
                    "mma.sync.aligned.m16n8k16.row.col.f32.f16.f16.f32 "
                    "{%0,%1,%2,%3}, {%4,%5,%6,%7}, {%8,%9}, {%0,%1,%2,%3};\n"
                    : "+f"(acc[mi][ni][0]), "+f"(acc[mi][ni][1]),
                      "+f"(acc[mi][ni][2]), "+f"(acc[mi][ni][3])
                    : "r"(af0[mi][0]), "r"(af0[mi][1]), "r"(af0[mi][2]), "r"(af0[mi][3]),
                      "r"(bf0[ni][0]), "r"(bf0[ni][1]));
            }
        // ---- h1 A frags ----
        #pragma unroll
        for (int mi = 0; mi < 2; mi++) {
            uint32_t addr = smA + ((wm * 32 + mi * 16 + a_row) * A_ROW_B) + (32 + a_ko * 16);
            asm volatile(
                "ldmatrix.sync.aligned.m8n8.x4.shared.b16 {%0,%1,%2,%3}, [%4];\n"
                : "=r"(af1[mi][0]), "=r"(af1[mi][1]), "=r"(af1[mi][2]), "=r"(af1[mi][3])
                : "r"(addr));
        }
        // ---- h1 MMAs ----
        #pragma unroll
        for (int mi = 0; mi < 2; mi++)
            #pragma unroll
            for (int ni = 0; ni < 8; ni++) {
                asm volatile(
                    "mma.sync.aligned.m16n8k16.row.col.f32.f16.f16.f32 "
                    "{%0,%1,%2,%3}, {%4,%5,%6,%7}, {%8,%9}, {%0,%1,%2,%3};\n"
                    : "+f"(acc[mi][ni][0]), "+f"(acc[mi][ni][1]),
                      "+f"(acc[mi][ni][2]), "+f"(acc[mi][ni][3])
                    : "r"(af1[mi][0]), "r"(af1[mi][1]), "r"(af1[mi][2]), "r"(af1[mi][3]),
                      "r"(bf1[ni][0]), "r"(bf1[ni][1]));
            }

        s_cur  = (s_cur  == STAGES - 1) ? 0 : s_cur + 1;
        s_load = (s_load == STAGES - 1) ? 0 : s_load + 1;
    }

    // ---------------- fused epilogue ----------------
    // rows: c0 + wm*32 + mi*16 + g (+8); cols: gx*BN + wn*64 + ni*8 + 2*t4 + p
    #pragma unroll
    for (int ni = 0; ni < 8; ni++) {
        #pragma unroll
        for (int p = 0; p < 2; p++) {
            const int n = gx * BN + wn * 64 + ni * 8 + t4 * 2 + p;
            const float* wdp = Wd + (size_t)n * 256 + c0 + wm * 32 + g;
            float s = 0.f;
            #pragma unroll
            for (int mi = 0; mi < 2; mi++) {
                s += acc[mi][ni][p]     * __ldg(wdp + mi * 16);
                s += acc[mi][ni][2 + p] * __ldg(wdp + mi * 16 + 8);
            }
            s += __shfl_xor_sync(0xffffffffu, s, 16);
            s += __shfl_xor_sync(0xffffffffu, s, 8);
            s += __shfl_xor_sync(0xffffffffu, s, 4);
            if (g == 0)
                atomicAdd(&out[(size_t)b * N_DIM + n], s);
        }
    }
}

extern "C" void kernel_launch(void* const* d_in, const int* in_sizes, int n_in,
                              void* d_out, int out_size) {
    const float* x  = (const float*)d_in[0];  // [8192 x 3136]
    const float* Ws = (const float*)d_in[1];  // [1024 x 3136]
    const float* Wd = (const float*)d_in[2];  // [1024 x 256]
    const float* Wb = (const float*)d_in[3];  // [1024]
    float* out = (float*)d_out;               // [32 x 1024] fp32

    static bool attr_set = false;
    if (!attr_set) {
        cudaFuncSetAttribute(gemm_fused,
                             cudaFuncAttributeMaxDynamicSharedMemorySize, SMEM_BYTES);
        attr_set = true;
    }

    prep_all<<<7058, 256>>>(x, Ws, Wb, out);  // x,Ws -> fp16; out = W_b
    dim3 grid(8, 64, 4);                      // 2048 CTAs
    gemm_fused<<<grid, 256, SMEM_BYTES>>>(Wd, out);
}

// round 14
// speedup vs baseline: 1.1113x; 1.1113x over previous
#include <cuda_runtime.h>
#include <cuda_fp16.h>
#include <cstdint>

// out[b,n] = sum_{c,hw} x[b,c,hw] * W_s[n,hw] * W_d[n,c] + W_b[n]
// GEMM D[(b,c),n] = x . Ws^T via fp16 mma.sync m16n8k16 (fp32 accum).
// Both operands pre-converted fp16 (streaming prep, MLP=8); all fragments via
// ldmatrix. BM=BN=128, 256 thr, 2 CTAs/SM, BK=64 (3 stages), quarter-rolling
// fragment prefetch. Split-K {832,768,768,768}. Fused Wd epilogue + atomics.

#define M_DIM 8192
#define N_DIM 1024
#define K_DIM 3136
#define BM 128
#define BN 128
#define BK 64
#define STAGES 3
#define ROW_B 144                      // 64 halfs (128B) + 16B pad -> conflict-free
#define A_ST_BYTES (128 * ROW_B)       // 18432
#define ST_BYTES   (2 * A_ST_BYTES)    // 36864
#define SMEM_BYTES (STAGES * ST_BYTES) // 110592 (x2 CTA = 216KB/SM)

__device__ __align__(16) __half g_Ah[(size_t)M_DIM * K_DIM];  // 51.4 MB fp16 x
__device__ __align__(16) __half g_Bh[(size_t)N_DIM * K_DIM];  // 6.4 MB fp16 Ws

__device__ __forceinline__ void cp_async16(void* s, const void* g) {
    uint32_t sa = (uint32_t)__cvta_generic_to_shared(s);
    asm volatile("cp.async.cg.shared.global [%0], [%1], 16;\n" :: "r"(sa), "l"(g));
}
__device__ __forceinline__ uint32_t pack_h2(float lo, float hi) {
    __half2 h = __floats2half2_rn(lo, hi);
    return *reinterpret_cast<uint32_t*>(&h);
}

// -------- prep: x->fp16 (3136 blocks), Ws->fp16 (392), out=W_b (1) --------
__global__ __launch_bounds__(256)
void prep_all(const float* __restrict__ x, const float* __restrict__ Ws,
              const float* __restrict__ Wb, float* __restrict__ out) {
    const int bid = blockIdx.x;
    const int tid = threadIdx.x;
    if (bid < 3136) {                       // x: 6,422,528 float4s, 8/thread
        const size_t base = (size_t)bid * 2048 + tid;
        float4 v[8];
        #pragma unroll
        for (int j = 0; j < 8; j++)
            v[j] = reinterpret_cast<const float4*>(x)[base + j * 256];
        #pragma unroll
        for (int j = 0; j < 8; j++) {
            uint2 o;
            o.x = pack_h2(v[j].x, v[j].y);
            o.y = pack_h2(v[j].z, v[j].w);
            reinterpret_cast<uint2*>(g_Ah)[base + j * 256] = o;
        }
    } else if (bid < 3528) {                // Ws: 802,816 float4s, 8/thread
        const size_t base = (size_t)(bid - 3136) * 2048 + tid;
        float4 v[8];
        #pragma unroll
        for (int j = 0; j < 8; j++)
            v[j] = reinterpret_cast<const float4*>(Ws)[base + j * 256];
        #pragma unroll
        for (int j = 0; j < 8; j++) {
            uint2 o;
            o.x = pack_h2(v[j].x, v[j].y);
            o.y = pack_h2(v[j].z, v[j].w);
            reinterpret_cast<uint2*>(g_Bh)[base + j * 256] = o;
        }
    } else {                                // out init: 8192 float4s
        #pragma unroll
        for (int j = 0; j < 32; j++) {
            int oi = tid + j * 256;
            reinterpret_cast<float4*>(out)[oi] =
                reinterpret_cast<const float4*>(Wb)[oi & 255];
        }
    }
}

// ---------------- fused GEMM ----------------
__global__ __launch_bounds__(256, 2)
void gemm_fused(const float* __restrict__ Wd, float* __restrict__ out) {
    extern __shared__ char smem[];

    const int tid  = threadIdx.x;
    const int warp = tid >> 5;      // 0..7
    const int lane = tid & 31;
    const int wm   = warp & 3;      // 4 warps along M (32 rows)
    const int wn   = warp >> 2;     // 2 warps along N (64 cols)
    const int g    = lane >> 2;
    const int t4   = lane & 3;

    const int gx = blockIdx.x;      // 0..7  N tile
    const int gy = blockIdx.y;      // 0..63 M tile
    const int sp = blockIdx.z;      // 0..3  K split
    const int b  = gy >> 1;
    const int c0 = (gy & 1) * BM;

    const int kst  = (sp == 0) ? 0 : 832 + (sp - 1) * 768;
    const int NT64 = (sp == 0) ? 13 : 12;

    // cp.async: 1024 chunks each for A and B; 4/thread each
    const int crow = tid >> 3;                 // 0..31 (+32*i)
    const int ccol = (tid & 7) * 16;           // byte offset in row
    const __half* apt = g_Ah + (size_t)(gy * BM + crow) * K_DIM + kst + (ccol >> 1);
    const __half* bpt = g_Bh + (size_t)(gx * BN + crow) * K_DIM + kst + (ccol >> 1);

    // ldmatrix lane maps
    const int a_row  = (lane & 7) + ((lane >> 3) & 1) * 8;
    const int a_ko   = (lane >> 4) & 1;
    const int b_row  = ((lane >> 4) & 1) * 8 + (lane & 7);
    const int b_half = ((lane >> 3) & 1) * 8;

    float acc[2][8][4];
    #pragma unroll
    for (int i = 0; i < 2; i++)
        #pragma unroll
        for (int j = 0; j < 8; j++)
            #pragma unroll
            for (int k = 0; k < 4; k++) acc[i][j][k] = 0.f;

    auto load_stage = [&](int s, int kt) {
        char* st = smem + s * ST_BYTES;
        #pragma unroll
        for (int i = 0; i < 4; i++)
            cp_async16(st + (crow + 32 * i) * ROW_B + ccol,
                       apt + (size_t)32 * i * K_DIM + kt * 64);
        #pragma unroll
        for (int i = 0; i < 4; i++)
            cp_async16(st + A_ST_BYTES + (crow + 32 * i) * ROW_B + ccol,
                       bpt + (size_t)32 * i * K_DIM + kt * 64);
    };

    load_stage(0, 0);
    asm volatile("cp.async.commit_group;\n" ::: "memory");
    load_stage(1, 1);
    asm volatile("cp.async.commit_group;\n" ::: "memory");

    int s_cur = 0, s_load = 2;
    #pragma unroll 1
    for (int kt = 0; kt < NT64; ++kt) {
        asm volatile("cp.async.wait_group 1;\n" ::: "memory");
        __syncthreads();

        if (kt + 2 < NT64) load_stage(s_load, kt + 2);
        asm volatile("cp.async.commit_group;\n" ::: "memory");

        const uint32_t smA = (uint32_t)__cvta_generic_to_shared(smem + s_cur * ST_BYTES);
        const uint32_t smB = smA + A_ST_BYTES;

        uint32_t af[2][2][4], bf[2][8][2];

        // preload quarter 0
        #pragma unroll
        for (int np = 0; np < 4; np++) {
            uint32_t addr = smB + (wn * 64 + np * 16 + b_row) * ROW_B + b_half * 2;
            asm volatile(
                "ldmatrix.sync.aligned.m8n8.x4.shared.b16 {%0,%1,%2,%3}, [%4];\n"
                : "=r"(bf[0][2 * np][0]), "=r"(bf[0][2 * np][1]),
                  "=r"(bf[0][2 * np + 1][0]), "=r"(bf[0][2 * np + 1][1])
                : "r"(addr));
        }
        #pragma unroll
        for (int mi = 0; mi < 2; mi++) {
            uint32_t addr = smA + (wm * 32 + mi * 16 + a_row) * ROW_B + a_ko * 16;
            asm volatile(
                "ldmatrix.sync.aligned.m8n8.x4.shared.b16 {%0,%1,%2,%3}, [%4];\n"
                : "=r"(af[0][mi][0]), "=r"(af[0][mi][1]),
                  "=r"(af[0][mi][2]), "=r"(af[0][mi][3])
                : "r"(addr));
        }

        #pragma unroll
        for (int q = 0; q < 4; q++) {
            const int cb = q & 1, nb = cb ^ 1;
            // prefetch next-quarter B before this quarter's MMAs
            if (q < 3) {
                #pragma unroll
                for (int np = 0; np < 4; np++) {
                    uint32_t addr = smB + (wn * 64 + np * 16 + b_row) * ROW_B
                                  + (q + 1) * 32 + b_half * 2;
                    asm volatile(
                        "ldmatrix.sync.aligned.m8n8.x4.shared.b16 {%0,%1,%2,%3}, [%4];\n"
                        : "=r"(bf[nb][2 * np][0]), "=r"(bf[nb][2 * np][1]),
                          "=r"(bf[nb][2 * np + 1][0]), "=r"(bf[nb][2 * np + 1][1])
                        : "r"(addr));
                }
            }
            // MMAs mi=0
            #pragma unroll
            for (int ni = 0; ni < 8; ni++) {
                asm volatile(
                    "mma.sync.aligned.m16n8k16.row.col.f32.f16.f16.f32 "
                    "{%0,%1,%2,%3}, {%4,%5,%6,%7}, {%8,%9}, {%0,%1,%2,%3};\n"
                    : "+f"(acc[0][ni][0]), "+f"(acc[0][ni][1]),
                      "+f"(acc[0][ni][2]), "+f"(acc[0][ni][3])
                    : "r"(af[cb][0][0]), "r"(af[cb][0][1]),
                      "r"(af[cb][0][2]), "r"(af[cb][0][3]),
                      "r"(bf[cb][ni][0]), "r"(bf[cb][ni][1]));
            }
            // prefetch next-quarter A between the mi halves
            if (q < 3) {
                #pragma unroll
                for (int mi = 0; mi < 2; mi++) {
                    uint32_t addr = smA + (wm * 32 + mi * 16 + a_row) * ROW_B
                                  + (q + 1) * 32 + a_ko * 16;
                    asm volatile(
                        "ldmatrix.sync.aligned.m8n8.x4.shared.b16 {%0,%1,%2,%3}, [%4];\n"
                        : "=r"(af[nb][mi][0]), "=r"(af[nb][mi][1]),
                          "=r"(af[nb][mi][2]), "=r"(af[nb][mi][3])
                        : "r"(addr));
                }
            }
            // MMAs mi=1
            #pragma unroll
            for (int ni = 0; ni < 8; ni++) {
                asm volatile(
                    "mma.sync.aligned.m16n8k16.row.col.f32.f16.f16.f32 "
                    "{%0,%1,%2,%3}, {%4,%5,%6,%7}, {%8,%9}, {%0,%1,%2,%3};\n"
                    : "+f"(acc[1][ni][0]), "+f"(acc[1][ni][1]),
                      "+f"(acc[1][ni][2]), "+f"(acc[1][ni][3])
                    : "r"(af[cb][1][0]), "r"(af[cb][1][1]),
                      "r"(af[cb][1][2]), "r"(af[cb][1][3]),
                      "r"(bf[cb][ni][0]), "r"(bf[cb][ni][1]));
            }
        }

        s_cur  = (s_cur  == STAGES - 1) ? 0 : s_cur + 1;
        s_load = (s_load == STAGES - 1) ? 0 : s_load + 1;
    }

    // ---------------- fused epilogue ----------------
    // rows: c0 + wm*32 + mi*16 + g (+8); cols: gx*BN + wn*64 + ni*8 + 2*t4 + p
    #pragma unroll
    for (int ni = 0; ni < 8; ni++) {
        #pragma unroll
        for (int p = 0; p < 2; p++) {
            const int n = gx * BN + wn * 64 + ni * 8 + t4 * 2 + p;
            const float* wdp = Wd + (size_t)n * 256 + c0 + wm * 32 + g;
            float s = 0.f;
            #pragma unroll
            for (int mi = 0; mi < 2; mi++) {
                s += acc[mi][ni][p]     * __ldg(wdp + mi * 16);
                s += acc[mi][ni][2 + p] * __ldg(wdp + mi * 16 + 8);
            }
            s += __shfl_xor_sync(0xffffffffu, s, 16);
            s += __shfl_xor_sync(0xffffffffu, s, 8);
            s += __shfl_xor_sync(0xffffffffu, s, 4);
            if (g == 0)
                atomicAdd(&out[(size_t)b * N_DIM + n], s);
        }
    }
}

extern "C" void kernel_launch(void* const* d_in, const int* in_sizes, int n_in,
                              void* d_out, int out_size) {
    const float* x  = (const float*)d_in[0];  // [8192 x 3136]
    const float* Ws = (const float*)d_in[1];  // [1024 x 3136]
    const float* Wd = (const float*)d_in[2];  // [1024 x 256]
    const float* Wb = (const float*)d_in[3];  // [1024]
    float* out = (float*)d_out;               // [32 x 1024] fp32

    static bool attr_set = false;
    if (!attr_set) {
        cudaFuncSetAttribute(gemm_fused,
                             cudaFuncAttributeMaxDynamicSharedMemorySize, SMEM_BYTES);
        attr_set = true;
    }

    prep_all<<<3529, 256>>>(x, Ws, Wb, out);  // x,Ws -> fp16 (MLP=8); out = W_b
    dim3 grid(8, 64, 4);                      // 2048 CTAs
    gemm_fused<<<grid, 256, SMEM_BYTES>>>(Wd, out);
}